// round 5
// baseline (speedup 1.0000x reference)
#include <cuda_runtime.h>
#include <cuda_bf16.h>

// ---------------------------------------------------------------------------
// phi_{b,v}(d) = sum_r pref_r[b,v] * exp(-0.5/w_r^2 * (d - o_r)^2)
// tabulated per (b,v) as piecewise quadratics in GLOBAL form:
//   phi(d) ~= A_k + B_k*d + C_k*d^2   for d in [k*h, (k+1)*h)
// ---------------------------------------------------------------------------
#define KNOTS   512
#define DMAXF   16.0f
#define SLICES  4
#define KS      (KNOTS / SLICES)   // 128 intervals per build block

__device__ float4 g_table[2 * 128 * KNOTS];   // [B*MAXZ, KNOTS]

__device__ __forceinline__ float ex2f_fast(float x) {
    float y; asm("ex2.approx.ftz.f32 %0, %1;" : "=f"(y) : "f"(x)); return y;
}
__device__ __forceinline__ float sqrtf_fast(float x) {
    float y; asm("sqrt.approx.f32 %0, %1;" : "=f"(y) : "f"(x)); return y;
}

// ---------------------------------------------------------------------------
// Kernel 1 (fused): prefactor + table build. grid = (B*MAXZ)*SLICES, 256 thr.
// Latency-optimized:
//  - W staged to smem cooperatively (coalesced, 256 threads)
//  - prefactor dot split over 4 threads per r (16-deep chains + 2 shfl)
//  - phi sampling with 4 independent accumulators
// ---------------------------------------------------------------------------
template <int RR>
__global__ __launch_bounds__(256)
void build_all_kernel(const float* __restrict__ t,
                      const float* __restrict__ emb,
                      const float* __restrict__ W,
                      const float* __restrict__ r_off,
                      const float* __restrict__ r_wid,
                      const float* __restrict__ t_off,
                      const float* __restrict__ t_wid,
                      int A, int R, int MAXZ) {
    __shared__ float sW[4096];                    // A*R <= 4096
    __shared__ float sx[128];
    __shared__ float s_pref[64], s_k2[64], s_off[64];
    __shared__ float s_phi[2 * KS + 1];

    const float LOG2E = 1.4426950408889634f;
    int pv    = blockIdx.x / SLICES;
    int slice = blockIdx.x % SLICES;
    int b     = pv / MAXZ;
    int v     = pv % MAXZ;
    int tid   = threadIdx.x;
    int Ruse  = (RR > 0) ? RR : R;

    int AR = A * R;
    for (int idx = tid; idx < AR; idx += 256) sW[idx] = __ldg(&W[idx]);
    if (tid < A) {
        float tw = t_wid[tid];
        float dt = t[b] - t_off[tid];
        float c  = (-0.5f / (tw * tw)) * LOG2E;
        sx[tid] = emb[(size_t)v * A + tid] * ex2f_fast(c * dt * dt);
    }
    if (tid < Ruse) {
        float w = r_wid[tid];
        s_k2[tid]  = (-0.5f / (w * w)) * LOG2E;
        s_off[tid] = r_off[tid];
    }
    __syncthreads();

    // prefactor: 4 threads per r, each covers a = sub, sub+4, ... (strided)
    {
        int rr  = tid >> 2;            // candidate r
        int sub = tid & 3;
        int rc  = (rr < Ruse) ? rr : (Ruse - 1);
        float s = 0.0f;
        for (int a = sub; a < A; a += 4)
            s = fmaf(sx[a], sW[a * R + rc], s);
        s += __shfl_xor_sync(0xFFFFFFFFu, s, 1);
        s += __shfl_xor_sync(0xFFFFFFFFu, s, 2);
        if (sub == 0 && rr < Ruse) s_pref[rr] = s;
    }
    __syncthreads();

    const float hh = DMAXF / (float)KNOTS;
    int base = slice * KS;
    for (int p = tid; p < 2 * KS + 1; p += 256) {
        float d = (float)(base * 2 + p) * (0.5f * hh);
        float acc0 = 0.f, acc1 = 0.f, acc2 = 0.f, acc3 = 0.f;
        if (RR > 0) {
#pragma unroll
            for (int r = 0; r < RR; r += 4) {
                {
                    float dd = d - s_off[r];
                    acc0 = fmaf(s_pref[r], ex2f_fast(s_k2[r] * dd * dd), acc0);
                }
                if (r + 1 < RR) {
                    float dd = d - s_off[r + 1];
                    acc1 = fmaf(s_pref[r + 1], ex2f_fast(s_k2[r + 1] * dd * dd), acc1);
                }
                if (r + 2 < RR) {
                    float dd = d - s_off[r + 2];
                    acc2 = fmaf(s_pref[r + 2], ex2f_fast(s_k2[r + 2] * dd * dd), acc2);
                }
                if (r + 3 < RR) {
                    float dd = d - s_off[r + 3];
                    acc3 = fmaf(s_pref[r + 3], ex2f_fast(s_k2[r + 3] * dd * dd), acc3);
                }
            }
        } else {
            for (int r = 0; r < R; r++) {
                float dd = d - s_off[r];
                acc0 = fmaf(s_pref[r], ex2f_fast(s_k2[r] * dd * dd), acc0);
            }
        }
        s_phi[p] = (acc0 + acc1) + (acc2 + acc3);
    }
    __syncthreads();

    if (tid < KS) {
        float y0 = s_phi[2 * tid + 0];
        float ym = s_phi[2 * tid + 1];
        float y1 = s_phi[2 * tid + 2];
        float inv_h = 1.0f / hh;
        int   k  = base + tid;
        float d0 = (float)k * hh;
        float bl = (4.0f * ym - 3.0f * y0 - y1) * inv_h;
        float cl = 2.0f * (y1 - 2.0f * ym + y0) * (inv_h * inv_h);
        float Cg = cl;
        float Bg = bl - 2.0f * cl * d0;
        float Ag = y0 - bl * d0 + cl * d0 * d0;
        g_table[(size_t)pv * KNOTS + k] = make_float4(Ag, Bg, Cg, 0.0f);
    }
}

// ---------------------------------------------------------------------------
// Kernel 2: main pairwise kernel. One block of 128 threads per (b, i):
// 2048 blocks -> ~14 blocks/SM, occ ~87%. 2-way j ILP inside the loop.
// ---------------------------------------------------------------------------
__global__ __launch_bounds__(128)
void vf_main_kernel(const float* __restrict__ pos,
                    const int*   __restrict__ z,
                    float*       __restrict__ out,
                    int N, int MAXZ) {
    extern __shared__ float s_pos[];   // [3N] packed float3
    __shared__ float s_red[12];

    int b   = blockIdx.x / N;
    int i   = blockIdx.x % N;
    int tid = threadIdx.x;

    const float* posb = pos + (size_t)b * N * 3;
    int nvec = (3 * N) >> 2;
    const float4* posb4 = (const float4*)posb;
    for (int idx = tid; idx < nvec; idx += 128)
        ((float4*)s_pos)[idx] = __ldg(&posb4[idx]);
    for (int idx = 4 * nvec + tid; idx < 3 * N; idx += 128)
        s_pos[idx] = posb[idx];

    const float4* tab = g_table + (size_t)(b * MAXZ + z[i]) * KNOTS;
    __syncthreads();

    float pix = s_pos[3 * i + 0];
    float piy = s_pos[3 * i + 1];
    float piz = s_pos[3 * i + 2];

    const float inv_h  = (float)KNOTS / DMAXF;
    const float dclamp = DMAXF - 0.5f * (DMAXF / (float)KNOTS);

    float a0 = 0.f, a1 = 0.f, a2 = 0.f;
    float b0 = 0.f, b1 = 0.f, b2 = 0.f;

    for (int j = tid; j < N; j += 256) {
        // lane A: j
        {
            float rx = pix - s_pos[3 * j + 0];
            float ry = piy - s_pos[3 * j + 1];
            float rz = piz - s_pos[3 * j + 2];
            float d2 = fmaf(rx, rx, fmaf(ry, ry, fmaf(rz, rz, 1e-6f)));
            float d  = fminf(sqrtf_fast(d2), dclamp);
            int   k  = (int)(d * inv_h);
            float4 c = __ldg(&tab[k]);
            float phi = fmaf(fmaf(c.z, d, c.y), d, c.x);
            a0 = fmaf(phi, rx, a0);
            a1 = fmaf(phi, ry, a1);
            a2 = fmaf(phi, rz, a2);
        }
        // lane B: j + 128
        int j2 = j + 128;
        if (j2 < N) {
            float rx = pix - s_pos[3 * j2 + 0];
            float ry = piy - s_pos[3 * j2 + 1];
            float rz = piz - s_pos[3 * j2 + 2];
            float d2 = fmaf(rx, rx, fmaf(ry, ry, fmaf(rz, rz, 1e-6f)));
            float d  = fminf(sqrtf_fast(d2), dclamp);
            int   k  = (int)(d * inv_h);
            float4 c = __ldg(&tab[k]);
            float phi = fmaf(fmaf(c.z, d, c.y), d, c.x);
            b0 = fmaf(phi, rx, b0);
            b1 = fmaf(phi, ry, b1);
            b2 = fmaf(phi, rz, b2);
        }
    }
    a0 += b0; a1 += b1; a2 += b2;

#pragma unroll
    for (int off = 16; off > 0; off >>= 1) {
        a0 += __shfl_down_sync(0xFFFFFFFFu, a0, off);
        a1 += __shfl_down_sync(0xFFFFFFFFu, a1, off);
        a2 += __shfl_down_sync(0xFFFFFFFFu, a2, off);
    }
    int warp = tid >> 5, lane = tid & 31;
    if (lane == 0) {
        s_red[warp * 3 + 0] = a0;
        s_red[warp * 3 + 1] = a1;
        s_red[warp * 3 + 2] = a2;
    }
    __syncthreads();
    if (tid == 0) {
        float r0 = 0.f, r1 = 0.f, r2 = 0.f;
#pragma unroll
        for (int w = 0; w < 4; w++) {
            r0 += s_red[w * 3 + 0];
            r1 += s_red[w * 3 + 1];
            r2 += s_red[w * 3 + 2];
        }
        size_t o = ((size_t)b * N + i) * 3;
        out[o + 0] = r0 + pix;
        out[o + 1] = r1 + piy;
        out[o + 2] = r2 + piz;
    }
}

// ---------------------------------------------------------------------------
// Inputs (metadata order):
//  0 positions [B,N,3] f32, 1 t [B] f32, 2 z [N] i32, 3 emb [MAXZ,A] f32,
//  4 W [A,R] f32, 5 rad_off [R], 6 rad_wid [R], 7 time_off [A], 8 time_wid [A]
// ---------------------------------------------------------------------------
extern "C" void kernel_launch(void* const* d_in, const int* in_sizes, int n_in,
                              void* d_out, int out_size) {
    const float* positions = (const float*)d_in[0];
    const float* t         = (const float*)d_in[1];
    const int*   z         = (const int*)  d_in[2];
    const float* emb       = (const float*)d_in[3];
    const float* W         = (const float*)d_in[4];
    const float* r_off     = (const float*)d_in[5];
    const float* r_wid     = (const float*)d_in[6];
    const float* t_off     = (const float*)d_in[7];
    const float* t_wid     = (const float*)d_in[8];

    int B    = in_sizes[1];
    int N    = in_sizes[2];
    int R    = in_sizes[5];
    int A    = in_sizes[7];
    int MAXZ = in_sizes[3] / A;

    if (R == 50)
        build_all_kernel<50><<<B * MAXZ * SLICES, 256>>>(
            t, emb, W, r_off, r_wid, t_off, t_wid, A, R, MAXZ);
    else
        build_all_kernel<0><<<B * MAXZ * SLICES, 256>>>(
            t, emb, W, r_off, r_wid, t_off, t_wid, A, R, MAXZ);

    size_t smem = (size_t)3 * N * sizeof(float);
    vf_main_kernel<<<B * N, 128, smem>>>(positions, z, (float*)d_out, N, MAXZ);
}

// round 6
// speedup vs baseline: 1.1648x; 1.1648x over previous
#include <cuda_runtime.h>
#include <cuda_bf16.h>

// ---------------------------------------------------------------------------
// Single fused kernel. One block per (batch b, atom-type v):
//   phase 1: scan z for rows with z_i == v; stage positions of batch b
//   phase 2: prefactor pref[r] = sum_a emb[v,a]*time_rbf(t_b,a)*W[a,r]
//   phase 3: sample phi(d) = sum_r pref_r*exp(k2_r*(d-off_r)^2) at 2K+1 pts
//   phase 4: fit piecewise quadratic (global form A + B*d + C*d^2) -> smem
//   phase 5: warp-per-row pair loop, warp reduce, write out + residual
// ---------------------------------------------------------------------------
#define KNOTS 256
#define DMAXF 16.0f

__device__ __forceinline__ float ex2f_fast(float x) {
    float y; asm("ex2.approx.ftz.f32 %0, %1;" : "=f"(y) : "f"(x)); return y;
}
__device__ __forceinline__ float sqrtf_fast(float x) {
    float y; asm("sqrt.approx.f32 %0, %1;" : "=f"(y) : "f"(x)); return y;
}

template <int RR>
__global__ __launch_bounds__(256)
void vf_fused_kernel(const float* __restrict__ pos,
                     const int*   __restrict__ z,
                     const float* __restrict__ t,
                     const float* __restrict__ emb,
                     const float* __restrict__ W,
                     const float* __restrict__ r_off,
                     const float* __restrict__ r_wid,
                     const float* __restrict__ t_off,
                     const float* __restrict__ t_wid,
                     float*       __restrict__ out,
                     int N, int A, int R, int MAXZ) {
    // dynamic smem layout: [3N floats pos][N ints rows][A*R floats W]
    extern __shared__ float smem[];
    float* s_pos  = smem;
    int*   s_rows = (int*)(smem + 3 * N);
    float* s_W    = (float*)(s_rows + N);

    __shared__ float4 s_tab[KNOTS];
    __shared__ float  s_phi[2 * KNOTS + 1];
    __shared__ float  sx[128];
    __shared__ float  s_pref[64], s_k2[64], s_off[64];
    __shared__ int    s_count;

    const float LOG2E = 1.4426950408889634f;
    int bv  = blockIdx.x;
    int b   = bv / MAXZ;
    int v   = bv % MAXZ;
    int tid = threadIdx.x;
    int Ruse = (RR > 0) ? RR : R;

    if (tid == 0) s_count = 0;
    __syncthreads();

    // ---- phase 1: row scan + staging (independent work, same pass) ----
    for (int i = tid; i < N; i += 256) {
        if (__ldg(&z[i]) == v) {
            int idx = atomicAdd(&s_count, 1);
            s_rows[idx] = i;
        }
    }
    const float* posb = pos + (size_t)b * N * 3;
    int nvec = (3 * N) >> 2;
    for (int idx = tid; idx < nvec; idx += 256)
        ((float4*)s_pos)[idx] = __ldg(((const float4*)posb) + idx);
    for (int idx = 4 * nvec + tid; idx < 3 * N; idx += 256)
        s_pos[idx] = posb[idx];
    int AR = A * R;
    for (int idx = tid; idx < AR; idx += 256)
        s_W[idx] = __ldg(&W[idx]);

    if (tid < A) {
        float tw = t_wid[tid];
        float dt = t[b] - t_off[tid];
        float c  = (-0.5f / (tw * tw)) * LOG2E;
        sx[tid] = emb[(size_t)v * A + tid] * ex2f_fast(c * dt * dt);
    }
    if (tid < Ruse) {
        float w = r_wid[tid];
        s_k2[tid]  = (-0.5f / (w * w)) * LOG2E;
        s_off[tid] = r_off[tid];
    }
    __syncthreads();

    if (s_count == 0) return;    // uniform across block (post-barrier)

    // ---- phase 2: prefactor, 4 threads per r ----
    {
        int rr  = tid >> 2;
        int sub = tid & 3;
        int rc  = (rr < Ruse) ? rr : (Ruse - 1);
        float s = 0.0f;
        for (int a = sub; a < A; a += 4)
            s = fmaf(sx[a], s_W[a * R + rc], s);
        s += __shfl_xor_sync(0xFFFFFFFFu, s, 1);
        s += __shfl_xor_sync(0xFFFFFFFFu, s, 2);
        if (sub == 0 && rr < Ruse) s_pref[rr] = s;
    }
    __syncthreads();

    // ---- phase 3: sample phi at 2*KNOTS+1 points ----
    const float hh = DMAXF / (float)KNOTS;
    for (int p = tid; p < 2 * KNOTS + 1; p += 256) {
        float d = (float)p * (0.5f * hh);
        float acc0 = 0.f, acc1 = 0.f, acc2 = 0.f, acc3 = 0.f;
        if (RR > 0) {
#pragma unroll
            for (int r = 0; r < RR; r += 4) {
                { float dd = d - s_off[r];
                  acc0 = fmaf(s_pref[r], ex2f_fast(s_k2[r] * dd * dd), acc0); }
                if (r + 1 < RR) { float dd = d - s_off[r + 1];
                  acc1 = fmaf(s_pref[r + 1], ex2f_fast(s_k2[r + 1] * dd * dd), acc1); }
                if (r + 2 < RR) { float dd = d - s_off[r + 2];
                  acc2 = fmaf(s_pref[r + 2], ex2f_fast(s_k2[r + 2] * dd * dd), acc2); }
                if (r + 3 < RR) { float dd = d - s_off[r + 3];
                  acc3 = fmaf(s_pref[r + 3], ex2f_fast(s_k2[r + 3] * dd * dd), acc3); }
            }
        } else {
            for (int r = 0; r < R; r++) {
                float dd = d - s_off[r];
                acc0 = fmaf(s_pref[r], ex2f_fast(s_k2[r] * dd * dd), acc0);
            }
        }
        s_phi[p] = (acc0 + acc1) + (acc2 + acc3);
    }
    __syncthreads();

    // ---- phase 4: fit quadratics, convert to global form ----
    if (tid < KNOTS) {
        float y0 = s_phi[2 * tid + 0];
        float ym = s_phi[2 * tid + 1];
        float y1 = s_phi[2 * tid + 2];
        float inv_h = 1.0f / hh;
        float d0 = (float)tid * hh;
        float bl = (4.0f * ym - 3.0f * y0 - y1) * inv_h;
        float cl = 2.0f * (y1 - 2.0f * ym + y0) * (inv_h * inv_h);
        float Cg = cl;
        float Bg = bl - 2.0f * cl * d0;
        float Ag = y0 - bl * d0 + cl * d0 * d0;
        s_tab[tid] = make_float4(Ag, Bg, Cg, 0.0f);
    }
    __syncthreads();

    // ---- phase 5: warp-per-row pair loop ----
    const float inv_h  = (float)KNOTS / DMAXF;
    const float dclamp = DMAXF - 0.5f * hh;
    int count = s_count;
    int warp  = tid >> 5;
    int lane  = tid & 31;

    for (int ri = warp; ri < count; ri += 8) {
        int i = s_rows[ri];
        float pix = s_pos[3 * i + 0];
        float piy = s_pos[3 * i + 1];
        float piz = s_pos[3 * i + 2];

        float a0 = 0.f, a1 = 0.f, a2 = 0.f;
        float b0 = 0.f, b1 = 0.f, b2 = 0.f;
        for (int j = lane; j < N; j += 64) {
            {
                float rx = pix - s_pos[3 * j + 0];
                float ry = piy - s_pos[3 * j + 1];
                float rz = piz - s_pos[3 * j + 2];
                float d2 = fmaf(rx, rx, fmaf(ry, ry, fmaf(rz, rz, 1e-6f)));
                float d  = fminf(sqrtf_fast(d2), dclamp);
                int   k  = (int)(d * inv_h);
                float4 c = s_tab[k];
                float phi = fmaf(fmaf(c.z, d, c.y), d, c.x);
                a0 = fmaf(phi, rx, a0);
                a1 = fmaf(phi, ry, a1);
                a2 = fmaf(phi, rz, a2);
            }
            int j2 = j + 32;
            if (j2 < N) {
                float rx = pix - s_pos[3 * j2 + 0];
                float ry = piy - s_pos[3 * j2 + 1];
                float rz = piz - s_pos[3 * j2 + 2];
                float d2 = fmaf(rx, rx, fmaf(ry, ry, fmaf(rz, rz, 1e-6f)));
                float d  = fminf(sqrtf_fast(d2), dclamp);
                int   k  = (int)(d * inv_h);
                float4 c = s_tab[k];
                float phi = fmaf(fmaf(c.z, d, c.y), d, c.x);
                b0 = fmaf(phi, rx, b0);
                b1 = fmaf(phi, ry, b1);
                b2 = fmaf(phi, rz, b2);
            }
        }
        a0 += b0; a1 += b1; a2 += b2;
#pragma unroll
        for (int off = 16; off > 0; off >>= 1) {
            a0 += __shfl_down_sync(0xFFFFFFFFu, a0, off);
            a1 += __shfl_down_sync(0xFFFFFFFFu, a1, off);
            a2 += __shfl_down_sync(0xFFFFFFFFu, a2, off);
        }
        if (lane == 0) {
            size_t o = ((size_t)b * N + i) * 3;
            out[o + 0] = a0 + pix;
            out[o + 1] = a1 + piy;
            out[o + 2] = a2 + piz;
        }
    }
}

// ---------------------------------------------------------------------------
// Inputs (metadata order):
//  0 positions [B,N,3] f32, 1 t [B] f32, 2 z [N] i32, 3 emb [MAXZ,A] f32,
//  4 W [A,R] f32, 5 rad_off [R], 6 rad_wid [R], 7 time_off [A], 8 time_wid [A]
// ---------------------------------------------------------------------------
extern "C" void kernel_launch(void* const* d_in, const int* in_sizes, int n_in,
                              void* d_out, int out_size) {
    const float* positions = (const float*)d_in[0];
    const float* t         = (const float*)d_in[1];
    const int*   z         = (const int*)  d_in[2];
    const float* emb       = (const float*)d_in[3];
    const float* W         = (const float*)d_in[4];
    const float* r_off     = (const float*)d_in[5];
    const float* r_wid     = (const float*)d_in[6];
    const float* t_off     = (const float*)d_in[7];
    const float* t_wid     = (const float*)d_in[8];

    int B    = in_sizes[1];
    int N    = in_sizes[2];
    int R    = in_sizes[5];
    int A    = in_sizes[7];
    int MAXZ = in_sizes[3] / A;

    // dynamic smem: 3N floats (pos) + N ints (rows) + A*R floats (W)
    size_t smem = (size_t)3 * N * sizeof(float) + (size_t)N * sizeof(int)
                + (size_t)A * R * sizeof(float);

    if (R == 50)
        vf_fused_kernel<50><<<B * MAXZ, 256, smem>>>(
            positions, z, t, emb, W, r_off, r_wid, t_off, t_wid,
            (float*)d_out, N, A, R, MAXZ);
    else
        vf_fused_kernel<0><<<B * MAXZ, 256, smem>>>(
            positions, z, t, emb, W, r_off, r_wid, t_off, t_wid,
            (float*)d_out, N, A, R, MAXZ);
}

// round 7
// speedup vs baseline: 1.4324x; 1.2297x over previous
#include <cuda_runtime.h>
#include <cuda_bf16.h>

// ---------------------------------------------------------------------------
// Single fused kernel. One block of 512 threads per (batch b, atom-type v):
//   phase 1: scan z for rows with z_i == v; stage positions + W to smem
//   phase 2: prefactor pref[r] = sum_a emb[v,a]*time_rbf(t_b,a)*W[a,r]
//   phase 3: sample phi(d) = sum_r pref_r*exp(k2_r*(d-off_r)^2) at 2K+1 pts
//   phase 4: fit piecewise quadratic (global form A + B*d + C*d^2) -> smem
//   phase 5: pair loop, C j-chunks per row across 16 warps, deterministic
//            fixed-order combine, write out + residual
// ---------------------------------------------------------------------------
#define KNOTS 128
#define DMAXF 16.0f

__device__ __forceinline__ float ex2f_fast(float x) {
    float y; asm("ex2.approx.ftz.f32 %0, %1;" : "=f"(y) : "f"(x)); return y;
}
__device__ __forceinline__ float sqrtf_fast(float x) {
    float y; asm("sqrt.approx.f32 %0, %1;" : "=f"(y) : "f"(x)); return y;
}

template <int RR>
__global__ __launch_bounds__(512)
void vf_fused_kernel(const float* __restrict__ pos,
                     const int*   __restrict__ z,
                     const float* __restrict__ t,
                     const float* __restrict__ emb,
                     const float* __restrict__ W,
                     const float* __restrict__ r_off,
                     const float* __restrict__ r_wid,
                     const float* __restrict__ t_off,
                     const float* __restrict__ t_wid,
                     float*       __restrict__ out,
                     int N, int A, int R, int MAXZ) {
    // dynamic smem: [3N floats pos][A*R floats W][N ints rows]
    extern __shared__ float smem[];
    float* s_pos  = smem;
    float* s_W    = smem + 3 * N;
    int*   s_rows = (int*)(s_W + A * R);

    __shared__ float4 s_tab[KNOTS];
    __shared__ float  s_phi[2 * KNOTS + 1];
    __shared__ float  sx[128];
    __shared__ float  s_pref[64], s_k2[64], s_off[64];
    __shared__ float  s_part[128 * 3];
    __shared__ int    s_count;

    const float LOG2E = 1.4426950408889634f;
    int bv  = blockIdx.x;
    int b   = bv / MAXZ;
    int v   = bv % MAXZ;
    int tid = threadIdx.x;
    int Ruse = (RR > 0) ? RR : R;
    int Rpad = (Ruse + 3) & ~3;          // padded loop bound (<= 64)

    if (tid == 0) s_count = 0;
    __syncthreads();

    // ---- phase 1: row scan + staging ----
    for (int i = tid; i < N; i += 512) {
        if (__ldg(&z[i]) == v) {
            int idx = atomicAdd(&s_count, 1);
            s_rows[idx] = i;
        }
    }
    const float* posb = pos + (size_t)b * N * 3;
    int nvec = (3 * N) >> 2;
    for (int idx = tid; idx < nvec; idx += 512)
        ((float4*)s_pos)[idx] = __ldg(((const float4*)posb) + idx);
    for (int idx = 4 * nvec + tid; idx < 3 * N; idx += 512)
        s_pos[idx] = posb[idx];
    int AR = A * R;
    for (int idx = tid; idx < AR; idx += 512)
        s_W[idx] = __ldg(&W[idx]);

    if (tid < A) {
        float tw = t_wid[tid];
        float dt = t[b] - t_off[tid];
        float c  = (-0.5f / (tw * tw)) * LOG2E;
        sx[tid] = emb[(size_t)v * A + tid] * ex2f_fast(c * dt * dt);
    }
    if (tid < 64) {
        if (tid < Ruse) {
            float w = r_wid[tid];
            s_k2[tid]  = (-0.5f / (w * w)) * LOG2E;
            s_off[tid] = r_off[tid];
        } else {
            s_k2[tid]  = -1.0f;     // padding: pref=0 makes it inert
            s_off[tid] = 0.0f;
            s_pref[tid] = 0.0f;
        }
    }
    __syncthreads();

    int count = s_count;
    if (count == 0) return;   // uniform across block

    // ---- phase 2: prefactor, 8 threads per r ----
    if (tid < 8 * 64) {
        int rr  = tid >> 3;
        int sub = tid & 7;
        int rc  = (rr < Ruse) ? rr : (Ruse - 1);
        float s = 0.0f;
        for (int a = sub; a < A; a += 8)
            s = fmaf(sx[a], s_W[a * R + rc], s);
        s += __shfl_xor_sync(0xFFFFFFFFu, s, 1);
        s += __shfl_xor_sync(0xFFFFFFFFu, s, 2);
        s += __shfl_xor_sync(0xFFFFFFFFu, s, 4);
        if (sub == 0 && rr < Ruse) s_pref[rr] = s;
    }
    __syncthreads();

    // ---- phase 3: sample phi at 2*KNOTS+1 points (padded, branch-free) ----
    const float hh = DMAXF / (float)KNOTS;
    for (int p = tid; p < 2 * KNOTS + 1; p += 512) {
        float d = (float)p * (0.5f * hh);
        float acc0 = 0.f, acc1 = 0.f, acc2 = 0.f, acc3 = 0.f;
#pragma unroll 1
        for (int r = 0; r < Rpad; r += 4) {
            float d0 = d - s_off[r + 0];
            float d1 = d - s_off[r + 1];
            float d2 = d - s_off[r + 2];
            float d3 = d - s_off[r + 3];
            acc0 = fmaf(s_pref[r + 0], ex2f_fast(s_k2[r + 0] * d0 * d0), acc0);
            acc1 = fmaf(s_pref[r + 1], ex2f_fast(s_k2[r + 1] * d1 * d1), acc1);
            acc2 = fmaf(s_pref[r + 2], ex2f_fast(s_k2[r + 2] * d2 * d2), acc2);
            acc3 = fmaf(s_pref[r + 3], ex2f_fast(s_k2[r + 3] * d3 * d3), acc3);
        }
        s_phi[p] = (acc0 + acc1) + (acc2 + acc3);
    }
    __syncthreads();

    // ---- phase 4: fit quadratics, convert to global form ----
    if (tid < KNOTS) {
        float y0 = s_phi[2 * tid + 0];
        float ym = s_phi[2 * tid + 1];
        float y1 = s_phi[2 * tid + 2];
        float inv_h = 1.0f / hh;
        float d0 = (float)tid * hh;
        float bl = (4.0f * ym - 3.0f * y0 - y1) * inv_h;
        float cl = 2.0f * (y1 - 2.0f * ym + y0) * (inv_h * inv_h);
        float Cg = cl;
        float Bg = bl - 2.0f * cl * d0;
        float Ag = y0 - bl * d0 + cl * d0 * d0;
        s_tab[tid] = make_float4(Ag, Bg, Cg, 0.0f);
    }
    __syncthreads();

    // ---- phase 5: pair loop. Each row split into C j-chunks (C in {1,2,4})
    //      so items = count*C keeps all 16 warps busy. Deterministic:
    //      partition and combine order fixed by (count, N) only. ----
    const float inv_h  = (float)KNOTS / DMAXF;
    const float dclamp = DMAXF - 0.5f * hh;
    int lg = (count * 4 <= 128) ? 2 : ((count * 2 <= 128) ? 1 : 0);
    int C  = 1 << lg;
    int items = count << lg;
    int warp = tid >> 5;
    int lane = tid & 31;

    for (int it = warp; it < items; it += 16) {
        int ri = it >> lg;
        int ch = it & (C - 1);
        int i  = s_rows[ri];
        float pix = s_pos[3 * i + 0];
        float piy = s_pos[3 * i + 1];
        float piz = s_pos[3 * i + 2];

        int j0 = (int)(((long long)N * ch) >> lg);
        int j1 = (int)(((long long)N * (ch + 1)) >> lg);

        float a0 = 0.f, a1 = 0.f, a2 = 0.f;
        float b0 = 0.f, b1 = 0.f, b2 = 0.f;
        for (int j = j0 + lane; j < j1; j += 64) {
            {
                float rx = pix - s_pos[3 * j + 0];
                float ry = piy - s_pos[3 * j + 1];
                float rz = piz - s_pos[3 * j + 2];
                float d2 = fmaf(rx, rx, fmaf(ry, ry, fmaf(rz, rz, 1e-6f)));
                float d  = fminf(sqrtf_fast(d2), dclamp);
                int   k  = (int)(d * inv_h);
                float4 c = s_tab[k];
                float phi = fmaf(fmaf(c.z, d, c.y), d, c.x);
                a0 = fmaf(phi, rx, a0);
                a1 = fmaf(phi, ry, a1);
                a2 = fmaf(phi, rz, a2);
            }
            int j2 = j + 32;
            if (j2 < j1) {
                float rx = pix - s_pos[3 * j2 + 0];
                float ry = piy - s_pos[3 * j2 + 1];
                float rz = piz - s_pos[3 * j2 + 2];
                float d2 = fmaf(rx, rx, fmaf(ry, ry, fmaf(rz, rz, 1e-6f)));
                float d  = fminf(sqrtf_fast(d2), dclamp);
                int   k  = (int)(d * inv_h);
                float4 c = s_tab[k];
                float phi = fmaf(fmaf(c.z, d, c.y), d, c.x);
                b0 = fmaf(phi, rx, b0);
                b1 = fmaf(phi, ry, b1);
                b2 = fmaf(phi, rz, b2);
            }
        }
        a0 += b0; a1 += b1; a2 += b2;
#pragma unroll
        for (int off = 16; off > 0; off >>= 1) {
            a0 += __shfl_down_sync(0xFFFFFFFFu, a0, off);
            a1 += __shfl_down_sync(0xFFFFFFFFu, a1, off);
            a2 += __shfl_down_sync(0xFFFFFFFFu, a2, off);
        }
        if (lane == 0) {
            if (C == 1) {
                size_t o = ((size_t)b * N + i) * 3;
                out[o + 0] = a0 + pix;
                out[o + 1] = a1 + piy;
                out[o + 2] = a2 + piz;
            } else {
                s_part[it * 3 + 0] = a0;
                s_part[it * 3 + 1] = a1;
                s_part[it * 3 + 2] = a2;
            }
        }
    }

    if (C > 1) {
        __syncthreads();
        for (int ri = tid; ri < count; ri += 512) {
            int i = s_rows[ri];
            float r0 = 0.f, r1 = 0.f, r2 = 0.f;
            for (int ch = 0; ch < C; ch++) {
                int it = (ri << lg) + ch;
                r0 += s_part[it * 3 + 0];
                r1 += s_part[it * 3 + 1];
                r2 += s_part[it * 3 + 2];
            }
            size_t o = ((size_t)b * N + i) * 3;
            out[o + 0] = r0 + s_pos[3 * i + 0];
            out[o + 1] = r1 + s_pos[3 * i + 1];
            out[o + 2] = r2 + s_pos[3 * i + 2];
        }
    }
}

// ---------------------------------------------------------------------------
// Inputs (metadata order):
//  0 positions [B,N,3] f32, 1 t [B] f32, 2 z [N] i32, 3 emb [MAXZ,A] f32,
//  4 W [A,R] f32, 5 rad_off [R], 6 rad_wid [R], 7 time_off [A], 8 time_wid [A]
// ---------------------------------------------------------------------------
extern "C" void kernel_launch(void* const* d_in, const int* in_sizes, int n_in,
                              void* d_out, int out_size) {
    const float* positions = (const float*)d_in[0];
    const float* t         = (const float*)d_in[1];
    const int*   z         = (const int*)  d_in[2];
    const float* emb       = (const float*)d_in[3];
    const float* W         = (const float*)d_in[4];
    const float* r_off     = (const float*)d_in[5];
    const float* r_wid     = (const float*)d_in[6];
    const float* t_off     = (const float*)d_in[7];
    const float* t_wid     = (const float*)d_in[8];

    int B    = in_sizes[1];
    int N    = in_sizes[2];
    int R    = in_sizes[5];
    int A    = in_sizes[7];
    int MAXZ = in_sizes[3] / A;

    // dynamic smem: 3N floats (pos) + A*R floats (W) + N ints (rows)
    size_t smem = (size_t)3 * N * sizeof(float)
                + (size_t)A * R * sizeof(float)
                + (size_t)N * sizeof(int);

    if (R == 50)
        vf_fused_kernel<50><<<B * MAXZ, 512, smem>>>(
            positions, z, t, emb, W, r_off, r_wid, t_off, t_wid,
            (float*)d_out, N, A, R, MAXZ);
    else
        vf_fused_kernel<0><<<B * MAXZ, 512, smem>>>(
            positions, z, t, emb, W, r_off, r_wid, t_off, t_wid,
            (float*)d_out, N, A, R, MAXZ);
}

// round 8
// speedup vs baseline: 1.5821x; 1.1045x over previous
#include <cuda_runtime.h>
#include <cuda_bf16.h>

// ---------------------------------------------------------------------------
// Single fused kernel. One block of 256 threads per (batch b, type v, slice):
//   - stage positions of batch b to smem
//   - scan slice's i-range for rows with z_i == v
//   - prefactor pref[r] = sum_a emb[v,a]*time_rbf(t_b,a)*W[a,r]
//   - sample phi(d) at 2*KNOTS+1 points, fit piecewise quadratic
//     (global form A + B*d + C*d^2) into smem table
//   - pair phase: each thread holds 4 j-positions in REGISTERS; whole block
//     processes each row; warp-shfl reduce + fixed-order 8-partial combine
// ---------------------------------------------------------------------------
#define KNOTS  64
#define DMAXF  16.0f
#define SLICES 4
#define TPB    256
#define NWARPS (TPB / 32)
#define RPASS  16

__device__ __forceinline__ float ex2f_fast(float x) {
    float y; asm("ex2.approx.ftz.f32 %0, %1;" : "=f"(y) : "f"(x)); return y;
}
__device__ __forceinline__ float sqrtf_fast(float x) {
    float y; asm("sqrt.approx.f32 %0, %1;" : "=f"(y) : "f"(x)); return y;
}

template <int RR>
__global__ __launch_bounds__(TPB)
void vf_fused_kernel(const float* __restrict__ pos,
                     const int*   __restrict__ z,
                     const float* __restrict__ t,
                     const float* __restrict__ emb,
                     const float* __restrict__ W,
                     const float* __restrict__ r_off,
                     const float* __restrict__ r_wid,
                     const float* __restrict__ t_off,
                     const float* __restrict__ t_wid,
                     float*       __restrict__ out,
                     int N, int A, int R, int MAXZ) {
    extern __shared__ float s_pos[];       // [3N]
    __shared__ float4 s_tab[KNOTS];
    __shared__ float  s_phi[2 * KNOTS + 1];
    __shared__ float  sx[128];
    __shared__ float  s_pref[64], s_k2[64], s_off[64];
    __shared__ int    s_rows[512];
    __shared__ float  s_part[RPASS][NWARPS][3];
    __shared__ int    s_count;

    const float LOG2E = 1.4426950408889634f;
    int bvs   = blockIdx.x;
    int bv    = bvs / SLICES;
    int slice = bvs % SLICES;
    int b     = bv / MAXZ;
    int v     = bv % MAXZ;
    int tid   = threadIdx.x;
    int Ruse  = (RR > 0) ? RR : R;
    int Rpad  = (Ruse + 3) & ~3;

    if (tid == 0) s_count = 0;
    __syncthreads();

    // ---- stage positions + scan slice range + small param prep ----
    const float* posb = pos + (size_t)b * N * 3;
    int nvec = (3 * N) >> 2;
    for (int idx = tid; idx < nvec; idx += TPB)
        ((float4*)s_pos)[idx] = __ldg(((const float4*)posb) + idx);
    for (int idx = 4 * nvec + tid; idx < 3 * N; idx += TPB)
        s_pos[idx] = posb[idx];

    int lo = (int)(((long long)N * slice) / SLICES);
    int hi = (int)(((long long)N * (slice + 1)) / SLICES);
    for (int i = lo + tid; i < hi; i += TPB) {
        if (__ldg(&z[i]) == v) {
            int idx = atomicAdd(&s_count, 1);
            if (idx < 512) s_rows[idx] = i;
        }
    }

    if (tid < A && tid < 128) {
        float tw = t_wid[tid];
        float dt = t[b] - t_off[tid];
        float c  = (-0.5f / (tw * tw)) * LOG2E;
        sx[tid] = emb[(size_t)v * A + tid] * ex2f_fast(c * dt * dt);
    }
    if (tid < 64) {
        if (tid < Ruse) {
            float w = r_wid[tid];
            s_k2[tid]  = (-0.5f / (w * w)) * LOG2E;
            s_off[tid] = r_off[tid];
        } else {
            s_k2[tid]  = -1.0f;     // padding: pref stays 0 -> inert
            s_off[tid] = 0.0f;
            s_pref[tid] = 0.0f;
        }
    }
    __syncthreads();

    int count = s_count;
    if (count == 0) return;          // uniform across block
    if (count > 512) count = 512;

    // ---- prefactor: 4 threads per r, W via __ldg (L2-hot across blocks) ----
    {
        int rr  = tid >> 2;
        int sub = tid & 3;
        int rc  = (rr < Ruse) ? rr : (Ruse - 1);
        float s = 0.0f;
        for (int a = sub; a < A; a += 4)
            s = fmaf(sx[a], __ldg(&W[(size_t)a * R + rc]), s);
        s += __shfl_xor_sync(0xFFFFFFFFu, s, 1);
        s += __shfl_xor_sync(0xFFFFFFFFu, s, 2);
        if (sub == 0 && rr < Ruse) s_pref[rr] = s;
    }
    __syncthreads();

    // ---- sample phi at 2*KNOTS+1 points (padded, branch-free) ----
    const float hh = DMAXF / (float)KNOTS;
    for (int p = tid; p < 2 * KNOTS + 1; p += TPB) {
        float d = (float)p * (0.5f * hh);
        float a0 = 0.f, a1 = 0.f, a2 = 0.f, a3 = 0.f;
#pragma unroll 1
        for (int r = 0; r < Rpad; r += 4) {
            float e0 = d - s_off[r + 0];
            float e1 = d - s_off[r + 1];
            float e2 = d - s_off[r + 2];
            float e3 = d - s_off[r + 3];
            a0 = fmaf(s_pref[r + 0], ex2f_fast(s_k2[r + 0] * e0 * e0), a0);
            a1 = fmaf(s_pref[r + 1], ex2f_fast(s_k2[r + 1] * e1 * e1), a1);
            a2 = fmaf(s_pref[r + 2], ex2f_fast(s_k2[r + 2] * e2 * e2), a2);
            a3 = fmaf(s_pref[r + 3], ex2f_fast(s_k2[r + 3] * e3 * e3), a3);
        }
        s_phi[p] = (a0 + a1) + (a2 + a3);
    }

    // ---- load this thread's 4 j-positions into registers (overlap) ----
    float jpx[4], jpy[4], jpz[4];
#pragma unroll
    for (int q = 0; q < 4; q++) {
        int j  = tid + q * TPB;
        int jj = (j < N) ? j : 0;
        jpx[q] = s_pos[3 * jj + 0];
        jpy[q] = s_pos[3 * jj + 1];
        jpz[q] = s_pos[3 * jj + 2];
    }
    __syncthreads();

    // ---- fit quadratics (global form) ----
    if (tid < KNOTS) {
        float y0 = s_phi[2 * tid + 0];
        float ym = s_phi[2 * tid + 1];
        float y1 = s_phi[2 * tid + 2];
        float inv_h = 1.0f / hh;
        float d0 = (float)tid * hh;
        float bl = (4.0f * ym - 3.0f * y0 - y1) * inv_h;
        float cl = 2.0f * (y1 - 2.0f * ym + y0) * (inv_h * inv_h);
        float Cg = cl;
        float Bg = bl - 2.0f * cl * d0;
        float Ag = y0 - bl * d0 + cl * d0 * d0;
        s_tab[tid] = make_float4(Ag, Bg, Cg, 0.0f);
    }
    __syncthreads();

    // ---- pair phase: whole block per row, j's from registers ----
    const float inv_h  = (float)KNOTS / DMAXF;
    const float dclamp = DMAXF - 0.5f * hh;
    int warp = tid >> 5, lane = tid & 31;

    for (int p0 = 0; p0 < count; p0 += RPASS) {
        int prn = count - p0; if (prn > RPASS) prn = RPASS;

        for (int pr = 0; pr < prn; pr++) {
            int i = s_rows[p0 + pr];
            float pix = s_pos[3 * i + 0];
            float piy = s_pos[3 * i + 1];
            float piz = s_pos[3 * i + 2];

            float a0 = 0.f, a1 = 0.f, a2 = 0.f;
#pragma unroll
            for (int q = 0; q < 4; q++) {
                int j = tid + q * TPB;
                if (j < N) {
                    float rx = pix - jpx[q];
                    float ry = piy - jpy[q];
                    float rz = piz - jpz[q];
                    float d2 = fmaf(rx, rx, fmaf(ry, ry, fmaf(rz, rz, 1e-6f)));
                    float d  = fminf(sqrtf_fast(d2), dclamp);
                    int   k  = (int)(d * inv_h);
                    float4 c = s_tab[k];
                    float phi = fmaf(fmaf(c.z, d, c.y), d, c.x);
                    a0 = fmaf(phi, rx, a0);
                    a1 = fmaf(phi, ry, a1);
                    a2 = fmaf(phi, rz, a2);
                }
            }
            // generic tail (N > 4*TPB): read from smem
            for (int j = 4 * TPB + tid; j < N; j += TPB) {
                float rx = pix - s_pos[3 * j + 0];
                float ry = piy - s_pos[3 * j + 1];
                float rz = piz - s_pos[3 * j + 2];
                float d2 = fmaf(rx, rx, fmaf(ry, ry, fmaf(rz, rz, 1e-6f)));
                float d  = fminf(sqrtf_fast(d2), dclamp);
                int   k  = (int)(d * inv_h);
                float4 c = s_tab[k];
                float phi = fmaf(fmaf(c.z, d, c.y), d, c.x);
                a0 = fmaf(phi, rx, a0);
                a1 = fmaf(phi, ry, a1);
                a2 = fmaf(phi, rz, a2);
            }
#pragma unroll
            for (int off = 16; off > 0; off >>= 1) {
                a0 += __shfl_down_sync(0xFFFFFFFFu, a0, off);
                a1 += __shfl_down_sync(0xFFFFFFFFu, a1, off);
                a2 += __shfl_down_sync(0xFFFFFFFFu, a2, off);
            }
            if (lane == 0) {
                s_part[pr][warp][0] = a0;
                s_part[pr][warp][1] = a1;
                s_part[pr][warp][2] = a2;
            }
        }
        __syncthreads();

        if (tid < prn) {
            int i = s_rows[p0 + tid];
            float r0 = 0.f, r1 = 0.f, r2 = 0.f;
#pragma unroll
            for (int w = 0; w < NWARPS; w++) {
                r0 += s_part[tid][w][0];
                r1 += s_part[tid][w][1];
                r2 += s_part[tid][w][2];
            }
            size_t o = ((size_t)b * N + i) * 3;
            out[o + 0] = r0 + s_pos[3 * i + 0];
            out[o + 1] = r1 + s_pos[3 * i + 1];
            out[o + 2] = r2 + s_pos[3 * i + 2];
        }
        __syncthreads();   // s_part reused next pass
    }
}

// ---------------------------------------------------------------------------
// Inputs (metadata order):
//  0 positions [B,N,3] f32, 1 t [B] f32, 2 z [N] i32, 3 emb [MAXZ,A] f32,
//  4 W [A,R] f32, 5 rad_off [R], 6 rad_wid [R], 7 time_off [A], 8 time_wid [A]
// ---------------------------------------------------------------------------
extern "C" void kernel_launch(void* const* d_in, const int* in_sizes, int n_in,
                              void* d_out, int out_size) {
    const float* positions = (const float*)d_in[0];
    const float* t         = (const float*)d_in[1];
    const int*   z         = (const int*)  d_in[2];
    const float* emb       = (const float*)d_in[3];
    const float* W         = (const float*)d_in[4];
    const float* r_off     = (const float*)d_in[5];
    const float* r_wid     = (const float*)d_in[6];
    const float* t_off     = (const float*)d_in[7];
    const float* t_wid     = (const float*)d_in[8];

    int B    = in_sizes[1];
    int N    = in_sizes[2];
    int R    = in_sizes[5];
    int A    = in_sizes[7];
    int MAXZ = in_sizes[3] / A;

    size_t smem = (size_t)3 * N * sizeof(float);
    int grid = B * MAXZ * SLICES;

    if (R == 50)
        vf_fused_kernel<50><<<grid, TPB, smem>>>(
            positions, z, t, emb, W, r_off, r_wid, t_off, t_wid,
            (float*)d_out, N, A, R, MAXZ);
    else
        vf_fused_kernel<0><<<grid, TPB, smem>>>(
            positions, z, t, emb, W, r_off, r_wid, t_off, t_wid,
            (float*)d_out, N, A, R, MAXZ);
}